// round 11
// baseline (speedup 1.0000x reference)
#include <cuda_runtime.h>
#include <cstdint>

#define RADIUS   4
#define MAX_DISP 192
#define BATCH    2
#define H        256
#define W        512
#define HC       248           // H - 8
#define WC       504           // W - 8
#define ROWBLKS  HC            // 248 (one output row per block)
#define NBLOCKS  (ROWBLKS * BATCH)  // 496 -> 4 blocks/SM, one wave on 148 SMs
#define TILE_H   (1 + 2 * RADIUS)   // 9
#define NTHREADS 256
#define GRPSZ    128
#define NQUADS   (WC / 4)      // 126 quads per group

// integer-exact accumulators; module-load init = 0, last block resets after use
__device__ unsigned int g_acc[2] = {0u, 0u};
__device__ unsigned int g_done = 0u;

extern __shared__ float smem_raw[];
// layout: lt[9*512] f32 | rt[9*512] f32 | sc0..sc3[504] u32 each

// v > c  ->  1.0f else 0.0f : single SASS FSET (no predicate).
__device__ __forceinline__ float fset_gt_f(float v, float c) {
    float r;
    asm("set.gt.f32.f32 %0, %1, %2;" : "=f"(r) : "f"(v), "f"(c));
    return r;
}

// Census for 4 consecutive pixels (cols wx..wx+3) from a 9x512 smem tile.
// 80 bits per pixel packed MSB-first into 4 words of 20 bits each, accumulated
// in fp32 (exact: values < 2^20 << 2^24) via FFMA-imm acc = acc*2 + bit.
// Bit order identical for left/right, which is all popc(XOR) needs.
__device__ __forceinline__ void census4(const float* __restrict__ t, int wx,
                                        unsigned a[4][4]) {
    const float4 cv = *(const float4*)&t[4 * W + wx + 4];
    const float c[4] = {cv.x, cv.y, cv.z, cv.w};
    float f[4][4];
    #pragma unroll
    for (int p = 0; p < 4; p++)
        #pragma unroll
        for (int w = 0; w < 4; w++) f[p][w] = 0.0f;

    int k = 0;
    #pragma unroll
    for (int i = 0; i < 9; i++) {
        const float4 v0 = *(const float4*)&t[i * W + wx];
        const float4 v1 = *(const float4*)&t[i * W + wx + 4];
        const float4 v2 = *(const float4*)&t[i * W + wx + 8];
        const float v[12] = {v0.x, v0.y, v0.z, v0.w,
                             v1.x, v1.y, v1.z, v1.w,
                             v2.x, v2.y, v2.z, v2.w};
        #pragma unroll
        for (int j = 0; j < 9; j++) {
            if (i == 4 && j == 4) continue;   // skip center (same k for all p)
            const int w = k / 20;             // compile-time after unroll
            #pragma unroll
            for (int p = 0; p < 4; p++) {
                const float bit = fset_gt_f(v[p + j], c[p]);   // ALU: FSET
                f[p][w] = fmaf(f[p][w], 2.0f, bit);            // FMA: FFMA-imm
            }
            k++;
        }
    }
    #pragma unroll
    for (int p = 0; p < 4; p++)
        #pragma unroll
        for (int w = 0; w < 4; w++) a[p][w] = (unsigned)f[p][w];   // exact F2I
}

__device__ __forceinline__ void group_bar(int id) {
    asm volatile("bar.sync %0, %1;" :: "r"(id), "r"(GRPSZ) : "memory");
}

// block: 256 flat (two 4-warp groups); grid: NBLOCKS, 4 blocks/SM, one wave
__global__ __launch_bounds__(NTHREADS, 4)
void fused_census_loss(const float* __restrict__ left,
                       const float* __restrict__ right,
                       const float* __restrict__ disp,
                       float* __restrict__ out) {
    float*    lt  = smem_raw;                         // 9*512 f32
    float*    rt  = smem_raw + TILE_H * W;            // 9*512 f32
    unsigned* sc0 = (unsigned*)(smem_raw + 2 * TILE_H * W);
    unsigned* sc1 = sc0 + WC;
    unsigned* sc2 = sc1 + WC;
    unsigned* sc3 = sc2 + WC;

    __shared__ unsigned s_red[2];

    const int blk = blockIdx.x;
    const int b   = blk / ROWBLKS;
    const int h0  = blk - b * ROWBLKS;           // output row (0..247)

    const int tid = threadIdx.x;                 // 0..255
    if (tid == 0) { s_red[0] = 0u; s_red[1] = 0u; }

    // two warp-aligned groups of 128; grp0: left(+gather), grp1: right
    const int  grp    = tid >> 7;
    const int  qid    = tid & (GRPSZ - 1);       // 0..127
    const bool active = (qid < NQUADS);
    const int  wx     = 4 * qid;

    // early independent global load (grp0 only; consumed after the full barrier)
    float4 dv = make_float4(0.f, 0.f, 0.f, 0.f);
    if (grp == 0 && active)
        dv = *(const float4*)&disp[((size_t)b * H + h0 + 4) * W + wx + 4];

    // ---- Phase A: each group loads only its own 9x512 tile ----
    {
        const float* src = (grp == 0 ? left : right) + (size_t)b * H * W + h0 * W;
        float*       dst = (grp == 0 ? lt : rt);
        const float4* s4 = (const float4*)src;
        float4*       d4 = (float4*)dst;
        #pragma unroll
        for (int i = qid; i < TILE_H * W / 4; i += GRPSZ)
            d4[i] = s4[i];
    }
    // group-local barrier: grp0 waits only on lt, grp1 only on rt
    group_bar(1 + grp);

    unsigned la[4][4];          // left census (grp0), carried across the barrier

    if (active) {
        if (grp == 0) {
            census4(lt, wx, la);
        } else {
            unsigned a[4][4];
            census4(rt, wx, a);
            *(uint4*)&sc0[wx] = make_uint4(a[0][0], a[1][0], a[2][0], a[3][0]);
            *(uint4*)&sc1[wx] = make_uint4(a[0][1], a[1][1], a[2][1], a[3][1]);
            *(uint4*)&sc2[wx] = make_uint4(a[0][2], a[1][2], a[2][2], a[3][2]);
            *(uint4*)&sc3[wx] = make_uint4(a[0][3], a[1][3], a[2][3], a[3][3]);
        }
    }

    __syncthreads();   // block-uniform: right-census stores visible to grp0

    unsigned cost = 0u, cnt = 0u;
    if (grp == 0 && active) {
        const float dd[4] = {dv.x, dv.y, dv.z, dv.w};
        #pragma unroll
        for (int p = 0; p < 4; p++) {
            if (dd[p] > 0.0f) {
                int ti = (int)dd[p];
                ti = ti < 0 ? 0 : (ti > MAX_DISP - 1 ? MAX_DISP - 1 : ti);
                const int widx = wx + p + ti;
                unsigned c;
                if (widx < WC) {
                    c = __popc(la[p][0] ^ sc0[widx]) +
                        __popc(la[p][1] ^ sc1[widx]) +
                        __popc(la[p][2] ^ sc2[widx]) +
                        __popc(la[p][3] ^ sc3[widx]);
                } else {
                    c = __popc(la[p][0]) + __popc(la[p][1]) +
                        __popc(la[p][2]) + __popc(la[p][3]);
                }
                cost += c;
                cnt  += 1u;
            }
        }
    }

    // ---- Reduce: warp shfl -> smem atomics -> global ----
    #pragma unroll
    for (int off = 16; off > 0; off >>= 1) {
        cost += __shfl_down_sync(0xFFFFFFFFu, cost, off);
        cnt  += __shfl_down_sync(0xFFFFFFFFu, cnt,  off);
    }
    if ((tid & 31) == 0 && grp == 0) {
        atomicAdd(&s_red[0], cost);
        atomicAdd(&s_red[1], cnt);
    }
    __syncthreads();

    if (tid == 0) {
        atomicAdd(&g_acc[0], s_red[0]);
        atomicAdd(&g_acc[1], s_red[1]);
        __threadfence();
        const unsigned prev = atomicAdd(&g_done, 1u);
        if (prev == NBLOCKS - 1u) {
            const unsigned tc = atomicAdd(&g_acc[0], 0u);
            const unsigned tn = atomicAdd(&g_acc[1], 0u);
            out[0] = (float)tc / ((float)tn + 1e-6f);
            // reset for the next graph replay (visible at next kernel launch)
            g_acc[0] = 0u;
            g_acc[1] = 0u;
            g_done   = 0u;
        }
    }
}

#define SMEM_BYTES (2 * TILE_H * W * 4 + 4 * WC * 4)   // 36864 + 8064 = 44928

extern "C" void kernel_launch(void* const* d_in, const int* in_sizes, int n_in,
                              void* d_out, int out_size) {
    const float* left  = (const float*)d_in[0];
    const float* right = (const float*)d_in[1];
    const float* disp  = (const float*)d_in[2];
    float* out = (float*)d_out;

    cudaFuncSetAttribute(fused_census_loss,
                         cudaFuncAttributeMaxDynamicSharedMemorySize, SMEM_BYTES);

    fused_census_loss<<<NBLOCKS, NTHREADS, SMEM_BYTES>>>(left, right, disp, out);
}

// round 12
// speedup vs baseline: 1.0408x; 1.0408x over previous
#include <cuda_runtime.h>
#include <cstdint>

#define RADIUS   4
#define MAX_DISP 192
#define BATCH    2
#define H        256
#define W        512
#define HC       248            // H - 8
#define WC       504            // W - 8
#define BH       2              // output rows per block
#define ROWBLKS  (HC / BH)      // 124
#define NBLOCKS  (ROWBLKS * BATCH)   // 248
#define TILE_H   (BH + 2 * RADIUS)   // 10
#define NTHREADS 512
#define GRPSZ    256
#define NQUADS   (BH * (WC / 4))     // 252 quads per image
#define SCW      (WC + MAX_DISP)     // 696 (zero-padded right census row)

// integer-exact accumulators; module-load init = 0, last block resets after use
__device__ unsigned int g_acc[2] = {0u, 0u};
__device__ unsigned int g_done = 0u;

extern __shared__ float smem_raw[];
// floats: lt[10*512] | rt[10*512]    (40960 B)
// uint4 : lc[2*504]                  (16128 B, left census, 1 uint4/pixel)
// uint4 : sc[2*696]                  (22272 B, right census + zero pad)
#define LC_OFF   (2 * TILE_H * W)          // float index
#define SC_OFF   (LC_OFF + 2 * WC * 4)     // float index (uint4 = 4 floats)
#define SMEM_BYTES ((SC_OFF + 2 * SCW * 4) * 4)   // 79360

// v > c  ->  1.0f else 0.0f : single SASS FSET (no predicate).
__device__ __forceinline__ float fset_gt_f(float v, float c) {
    float r;
    asm("set.gt.f32.f32 %0, %1, %2;" : "=f"(r) : "f"(v), "f"(c));
    return r;
}

// Census for 4 consecutive pixels (row rr, cols wx..wx+3) from a 10x512 tile.
// 80 bits per pixel packed MSB-first into 4 words of 20 bits each, accumulated
// in fp32 (exact: values < 2^20 << 2^24) via FFMA-imm acc = acc*2 + bit.
// Bit order identical for left/right, which is all popc(XOR) needs.
__device__ __forceinline__ void census4(const float* __restrict__ t, int rr, int wx,
                                        unsigned a[4][4]) {
    const float4 cv = *(const float4*)&t[(rr + 4) * W + wx + 4];
    const float c[4] = {cv.x, cv.y, cv.z, cv.w};
    float f[4][4];
    #pragma unroll
    for (int p = 0; p < 4; p++)
        #pragma unroll
        for (int w = 0; w < 4; w++) f[p][w] = 0.0f;

    int k = 0;
    #pragma unroll
    for (int i = 0; i < 9; i++) {
        const float4 v0 = *(const float4*)&t[(rr + i) * W + wx];
        const float4 v1 = *(const float4*)&t[(rr + i) * W + wx + 4];
        const float4 v2 = *(const float4*)&t[(rr + i) * W + wx + 8];
        const float v[12] = {v0.x, v0.y, v0.z, v0.w,
                             v1.x, v1.y, v1.z, v1.w,
                             v2.x, v2.y, v2.z, v2.w};
        #pragma unroll
        for (int j = 0; j < 9; j++) {
            if (i == 4 && j == 4) continue;   // skip center (same k for all p)
            const int w = k / 20;             // compile-time after unroll
            #pragma unroll
            for (int p = 0; p < 4; p++) {
                const float bit = fset_gt_f(v[p + j], c[p]);   // ALU: FSET
                f[p][w] = fmaf(f[p][w], 2.0f, bit);            // FMA: FFMA-imm
            }
            k++;
        }
    }
    #pragma unroll
    for (int p = 0; p < 4; p++)
        #pragma unroll
        for (int w = 0; w < 4; w++) a[p][w] = (unsigned)f[p][w];   // exact F2I
}

__device__ __forceinline__ void group_bar(int id) {
    asm volatile("bar.sync %0, %1;" :: "r"(id), "r"(GRPSZ) : "memory");
}

// block: 512 flat (two 8-warp groups); grid 248, 2 blocks/SM
__global__ __launch_bounds__(NTHREADS, 2)
void fused_census_loss(const float* __restrict__ left,
                       const float* __restrict__ right,
                       const float* __restrict__ disp,
                       float* __restrict__ out) {
    float* lt = smem_raw;                       // 10*512 f32
    float* rt = smem_raw + TILE_H * W;          // 10*512 f32
    uint4* lc = (uint4*)(smem_raw + LC_OFF);    // [2][504]
    uint4* sc = (uint4*)(smem_raw + SC_OFF);    // [2][696] (cols >=504 zero)

    __shared__ unsigned s_red[2];

    const int blk = blockIdx.x;
    const int b   = blk / ROWBLKS;
    const int h0  = (blk - b * ROWBLKS) * BH;

    const int tid = threadIdx.x;                // 0..511
    if (tid == 0) { s_red[0] = 0u; s_red[1] = 0u; }

    // two warp-aligned groups of 256; grp0: left census, grp1: right census
    const int  grp    = tid >> 8;
    const int  qid    = tid & (GRPSZ - 1);      // 0..255
    const bool active = (qid < NQUADS);
    const int  rr     = qid / 126;              // 0..1 (clamped by 'active')
    const int  wx     = 4 * (qid - rr * 126);

    // per-pixel disparity prefetch (gather is 1 column x 2 rows per thread)
    float dd0 = 0.f, dd1 = 0.f;
    if (tid < WC) {
        dd0 = disp[((size_t)b * H + h0 + 4) * W + tid + 4];
        dd1 = disp[((size_t)b * H + h0 + 5) * W + tid + 4];
    }

    // ---- Phase A: each group loads its own 10x512 tile; grp1 zeroes sc pad ----
    {
        const float* src = (grp == 0 ? left : right) + (size_t)b * H * W + h0 * W;
        float*       dst = (grp == 0 ? lt : rt);
        const float4* s4 = (const float4*)src;
        float4*       d4 = (float4*)dst;
        #pragma unroll
        for (int i = qid; i < TILE_H * W / 4; i += GRPSZ)
            d4[i] = s4[i];
        if (grp == 1) {
            // zero the 192-wide pad of both sc rows (2*192 = 384 uint4)
            for (int i = qid; i < 2 * MAX_DISP; i += GRPSZ) {
                const int r = i / MAX_DISP;
                const int c = WC + (i - r * MAX_DISP);
                sc[r * SCW + c] = make_uint4(0u, 0u, 0u, 0u);
            }
        }
    }
    group_bar(1 + grp);   // grp0 waits only on lt, grp1 only on rt

    if (active) {
        unsigned a[4][4];
        if (grp == 0) {
            census4(lt, rr, wx, a);
            #pragma unroll
            for (int p = 0; p < 4; p++)
                lc[rr * WC + wx + p] = make_uint4(a[p][0], a[p][1], a[p][2], a[p][3]);
        } else {
            census4(rt, rr, wx, a);
            #pragma unroll
            for (int p = 0; p < 4; p++)
                sc[rr * SCW + wx + p] = make_uint4(a[p][0], a[p][1], a[p][2], a[p][3]);
        }
    }

    __syncthreads();   // all census stores + pad visible to every thread

    // ---- Gather: 504 columns x 2 rows, one column per thread ----
    unsigned cost = 0u, cnt = 0u;
    if (tid < WC) {
        const float dd[2] = {dd0, dd1};
        #pragma unroll
        for (int r = 0; r < 2; r++) {
            if (dd[r] > 0.0f) {
                int ti = (int)dd[r];
                ti = ti < 0 ? 0 : (ti > MAX_DISP - 1 ? MAX_DISP - 1 : ti);
                const uint4 L = lc[r * WC + tid];
                const uint4 R = sc[r * SCW + tid + ti];   // pad -> zeros == no-match case
                cost += __popc(L.x ^ R.x) + __popc(L.y ^ R.y) +
                        __popc(L.z ^ R.z) + __popc(L.w ^ R.w);
                cnt  += 1u;
            }
        }
    }

    // ---- Reduce: warp shfl -> smem atomics -> global ----
    #pragma unroll
    for (int off = 16; off > 0; off >>= 1) {
        cost += __shfl_down_sync(0xFFFFFFFFu, cost, off);
        cnt  += __shfl_down_sync(0xFFFFFFFFu, cnt,  off);
    }
    if ((tid & 31) == 0) {
        atomicAdd(&s_red[0], cost);
        atomicAdd(&s_red[1], cnt);
    }
    __syncthreads();

    if (tid == 0) {
        atomicAdd(&g_acc[0], s_red[0]);
        atomicAdd(&g_acc[1], s_red[1]);
        __threadfence();
        const unsigned prev = atomicAdd(&g_done, 1u);
        if (prev == NBLOCKS - 1u) {
            const unsigned tc = atomicAdd(&g_acc[0], 0u);
            const unsigned tn = atomicAdd(&g_acc[1], 0u);
            out[0] = (float)tc / ((float)tn + 1e-6f);
            // reset for the next graph replay (visible at next kernel launch)
            g_acc[0] = 0u;
            g_acc[1] = 0u;
            g_done   = 0u;
        }
    }
}

extern "C" void kernel_launch(void* const* d_in, const int* in_sizes, int n_in,
                              void* d_out, int out_size) {
    const float* left  = (const float*)d_in[0];
    const float* right = (const float*)d_in[1];
    const float* disp  = (const float*)d_in[2];
    float* out = (float*)d_out;

    cudaFuncSetAttribute(fused_census_loss,
                         cudaFuncAttributeMaxDynamicSharedMemorySize, SMEM_BYTES);

    fused_census_loss<<<NBLOCKS, NTHREADS, SMEM_BYTES>>>(left, right, disp, out);
}

// round 13
// speedup vs baseline: 1.2143x; 1.1667x over previous
#include <cuda_runtime.h>
#include <cstdint>

#define RADIUS   4
#define MAX_DISP 192
#define BATCH    2
#define H        256
#define W        512
#define HC       248            // H - 8
#define WC       504            // W - 8
#define BH       2              // output rows per block
#define ROWBLKS  (HC / BH)      // 124
#define NBLOCKS  (ROWBLKS * BATCH)   // 248 -> 2 blocks/SM
#define NTHREADS 512
#define GRPSZ    256
#define NQUADS   (BH * (WC / 4))     // 252 quads per image
#define SCW      (WC + MAX_DISP)     // 696 (zero-padded right census row)

// integer-exact accumulators; module-load init = 0, last block resets after use
__device__ unsigned int g_acc[2] = {0u, 0u};
__device__ unsigned int g_done = 0u;

// v > c  ->  1.0f else 0.0f : single SASS FSET (no predicate).
__device__ __forceinline__ float fset_gt_f(float v, float c) {
    float r;
    asm("set.gt.f32.f32 %0, %1, %2;" : "=f"(r) : "f"(v), "f"(c));
    return r;
}

// Census for 4 consecutive pixels (cols wx..wx+3 of row base_row) read DIRECTLY
// from the global image (L1/L2 resident; loads overlap compute via scoreboard).
// 80 bits per pixel packed MSB-first into 4 words of 20 bits each, accumulated
// in fp32 (exact: values < 2^20 << 2^24) via FFMA-imm acc = acc*2 + bit.
// Bit order identical for left/right, which is all popc(XOR) needs.
__device__ __forceinline__ void census4g(const float* __restrict__ img,
                                         int base_row, int wx,
                                         unsigned a[4][4]) {
    const float* t = img + (size_t)base_row * W;
    const float4 cv = __ldg((const float4*)&t[4 * W + wx + 4]);
    const float c[4] = {cv.x, cv.y, cv.z, cv.w};
    float f[4][4];
    #pragma unroll
    for (int p = 0; p < 4; p++)
        #pragma unroll
        for (int w = 0; w < 4; w++) f[p][w] = 0.0f;

    int k = 0;
    #pragma unroll
    for (int i = 0; i < 9; i++) {
        const float4 v0 = __ldg((const float4*)&t[i * W + wx]);
        const float4 v1 = __ldg((const float4*)&t[i * W + wx + 4]);
        const float4 v2 = __ldg((const float4*)&t[i * W + wx + 8]);
        const float v[12] = {v0.x, v0.y, v0.z, v0.w,
                             v1.x, v1.y, v1.z, v1.w,
                             v2.x, v2.y, v2.z, v2.w};
        #pragma unroll
        for (int j = 0; j < 9; j++) {
            if (i == 4 && j == 4) continue;   // skip center (same k for all p)
            const int w = k / 20;             // compile-time after unroll
            #pragma unroll
            for (int p = 0; p < 4; p++) {
                const float bit = fset_gt_f(v[p + j], c[p]);   // ALU: FSET
                f[p][w] = fmaf(f[p][w], 2.0f, bit);            // FMA: FFMA-imm
            }
            k++;
        }
    }
    #pragma unroll
    for (int p = 0; p < 4; p++)
        #pragma unroll
        for (int w = 0; w < 4; w++) a[p][w] = (unsigned)f[p][w];   // exact F2I
}

// block: 512 flat (two 8-warp groups); grid 248, 2 blocks/SM
__global__ __launch_bounds__(NTHREADS, 2)
void fused_census_loss(const float* __restrict__ left,
                       const float* __restrict__ right,
                       const float* __restrict__ disp,
                       float* __restrict__ out) {
    // right census only (left stays in registers); cols >= WC are zero pad
    __shared__ uint4    sc[BH * SCW];     // 22272 B
    __shared__ unsigned s_red[2];

    const int blk = blockIdx.x;
    const int b   = blk / ROWBLKS;
    const int h0  = (blk - b * ROWBLKS) * BH;

    const int tid = threadIdx.x;                 // 0..511
    if (tid == 0) { s_red[0] = 0u; s_red[1] = 0u; }

    // zero the 192-wide pad of both sc rows (384 uint4) — before the barrier
    for (int i = tid; i < BH * MAX_DISP; i += NTHREADS) {
        const int r = i / MAX_DISP;
        const int c = WC + (i - r * MAX_DISP);
        sc[r * SCW + c] = make_uint4(0u, 0u, 0u, 0u);
    }

    // two warp-aligned groups of 256; grp0: left(+gather), grp1: right
    const int  grp    = tid >> 8;
    const int  qid    = tid & (GRPSZ - 1);       // 0..255
    const bool active = (qid < NQUADS);
    const int  rr     = qid / 126;               // 0..1 (clamped by 'active')
    const int  wx     = 4 * (qid - rr * 126);

    const size_t img_off = (size_t)b * H * W;

    unsigned la[4][4];          // left census (grp0), carried across the barrier
    float4 dv = make_float4(0.f, 0.f, 0.f, 0.f);

    if (active) {
        if (grp == 0) {
            // early independent load; consumed after the barrier
            dv = *(const float4*)&disp[img_off + (size_t)(h0 + rr + 4) * W + wx + 4];
            census4g(left + img_off, h0 + rr, wx, la);
        } else {
            unsigned a[4][4];
            census4g(right + img_off, h0 + rr, wx, a);
            #pragma unroll
            for (int p = 0; p < 4; p++)
                sc[rr * SCW + wx + p] = make_uint4(a[p][0], a[p][1], a[p][2], a[p][3]);
        }
    }

    __syncthreads();   // right-census stores + pad visible to grp0

    unsigned cost = 0u, cnt = 0u;
    if (grp == 0 && active) {
        const float dd[4] = {dv.x, dv.y, dv.z, dv.w};
        #pragma unroll
        for (int p = 0; p < 4; p++) {
            if (dd[p] > 0.0f) {
                int ti = (int)dd[p];
                ti = ti < 0 ? 0 : (ti > MAX_DISP - 1 ? MAX_DISP - 1 : ti);
                const uint4 R = sc[rr * SCW + wx + p + ti];  // pad zeros == OOR case
                cost += __popc(la[p][0] ^ R.x) + __popc(la[p][1] ^ R.y) +
                        __popc(la[p][2] ^ R.z) + __popc(la[p][3] ^ R.w);
                cnt  += 1u;
            }
        }
    }

    // ---- Reduce: warp shfl -> smem atomics -> global ----
    #pragma unroll
    for (int off = 16; off > 0; off >>= 1) {
        cost += __shfl_down_sync(0xFFFFFFFFu, cost, off);
        cnt  += __shfl_down_sync(0xFFFFFFFFu, cnt,  off);
    }
    if ((tid & 31) == 0 && grp == 0) {
        atomicAdd(&s_red[0], cost);
        atomicAdd(&s_red[1], cnt);
    }
    __syncthreads();

    if (tid == 0) {
        atomicAdd(&g_acc[0], s_red[0]);
        atomicAdd(&g_acc[1], s_red[1]);
        __threadfence();
        const unsigned prev = atomicAdd(&g_done, 1u);
        if (prev == NBLOCKS - 1u) {
            const unsigned tc = atomicAdd(&g_acc[0], 0u);
            const unsigned tn = atomicAdd(&g_acc[1], 0u);
            out[0] = (float)tc / ((float)tn + 1e-6f);
            // reset for the next graph replay (visible at next kernel launch)
            g_acc[0] = 0u;
            g_acc[1] = 0u;
            g_done   = 0u;
        }
    }
}

extern "C" void kernel_launch(void* const* d_in, const int* in_sizes, int n_in,
                              void* d_out, int out_size) {
    const float* left  = (const float*)d_in[0];
    const float* right = (const float*)d_in[1];
    const float* disp  = (const float*)d_in[2];
    float* out = (float*)d_out;

    fused_census_loss<<<NBLOCKS, NTHREADS>>>(left, right, disp, out);
}

// round 14
// speedup vs baseline: 1.2179x; 1.0030x over previous
#include <cuda_runtime.h>
#include <cstdint>

#define RADIUS   4
#define MAX_DISP 192
#define BATCH    2
#define H        256
#define W        512
#define HC       248            // H - 8
#define WC       504            // W - 8
#define ROWBLKS  HC             // one output row per block
#define NBLOCKS  (ROWBLKS * BATCH)   // 992 blocks -> ~6.7 per SM
#define NTHREADS 128
#define NQUADS   (WC / 4)       // 126 active threads
#define SCW      (WC + MAX_DISP)     // 696 (zero-padded right census row)

// integer-exact accumulators; module-load init = 0, last block resets after use
__device__ unsigned int g_acc[2] = {0u, 0u};
__device__ unsigned int g_done = 0u;

// v > c  ->  1.0f else 0.0f : single SASS FSET (no predicate).
__device__ __forceinline__ float fset_gt_f(float v, float c) {
    float r;
    asm("set.gt.f32.f32 %0, %1, %2;" : "=f"(r) : "f"(v), "f"(c));
    return r;
}

// Census for 4 consecutive pixels (cols wx..wx+3, output row h0) read directly
// from the global image (L1/L2 resident; loads overlap compute via scoreboard).
// 80 bits per pixel packed MSB-first into 4 words of 20 bits each, accumulated
// in fp32 (exact: values < 2^20 << 2^24) via FFMA-imm acc = acc*2 + bit.
// Bit order identical for left/right, which is all popc(XOR) needs.
__device__ __forceinline__ void census4g(const float* __restrict__ t, int wx,
                                         unsigned a[4][4]) {
    const float4 cv = __ldg((const float4*)&t[4 * W + wx + 4]);
    const float c[4] = {cv.x, cv.y, cv.z, cv.w};
    float f[4][4];
    #pragma unroll
    for (int p = 0; p < 4; p++)
        #pragma unroll
        for (int w = 0; w < 4; w++) f[p][w] = 0.0f;

    int k = 0;
    #pragma unroll
    for (int i = 0; i < 9; i++) {
        const float4 v0 = __ldg((const float4*)&t[i * W + wx]);
        const float4 v1 = __ldg((const float4*)&t[i * W + wx + 4]);
        const float4 v2 = __ldg((const float4*)&t[i * W + wx + 8]);
        const float v[12] = {v0.x, v0.y, v0.z, v0.w,
                             v1.x, v1.y, v1.z, v1.w,
                             v2.x, v2.y, v2.z, v2.w};
        #pragma unroll
        for (int j = 0; j < 9; j++) {
            if (i == 4 && j == 4) continue;   // skip center (same k for all p)
            const int w = k / 20;             // compile-time after unroll
            #pragma unroll
            for (int p = 0; p < 4; p++) {
                const float bit = fset_gt_f(v[p + j], c[p]);   // ALU: FSET
                f[p][w] = fmaf(f[p][w], 2.0f, bit);            // FMA: FFMA-imm
            }
            k++;
        }
    }
    #pragma unroll
    for (int p = 0; p < 4; p++)
        #pragma unroll
        for (int w = 0; w < 4; w++) a[p][w] = (unsigned)f[p][w];   // exact F2I
}

// block: 128 threads, one output row; each thread owns one quad and computes
// BOTH censuses (right -> smem, left -> registers). grid: 992, ~6.7 blocks/SM.
__global__ __launch_bounds__(NTHREADS, 8)
void fused_census_loss(const float* __restrict__ left,
                       const float* __restrict__ right,
                       const float* __restrict__ disp,
                       float* __restrict__ out) {
    __shared__ uint4    sc[SCW];      // right census + zero pad (11136 B)
    __shared__ unsigned s_red[2];

    const int blk = blockIdx.x;
    const int b   = blk / ROWBLKS;
    const int h0  = blk - b * ROWBLKS;           // output row (0..247)

    const int tid = threadIdx.x;                 // 0..127 (126 active)
    if (tid == 0) { s_red[0] = 0u; s_red[1] = 0u; }

    // zero the 192-wide pad (branch-free out-of-range gather)
    for (int i = tid; i < MAX_DISP; i += NTHREADS)
        sc[WC + i] = make_uint4(0u, 0u, 0u, 0u);

    const bool active = (tid < NQUADS);
    const int  wx     = 4 * tid;

    const size_t img_off = (size_t)b * H * W + (size_t)h0 * W;

    unsigned la[4][4];
    float4 dv = make_float4(0.f, 0.f, 0.f, 0.f);

    if (active) {
        // early independent load; consumed after the barrier
        dv = *(const float4*)&disp[img_off + 4 * W + wx + 4];

        // right census -> smem
        unsigned a[4][4];
        census4g(right + img_off, wx, a);
        #pragma unroll
        for (int p = 0; p < 4; p++)
            sc[wx + p] = make_uint4(a[p][0], a[p][1], a[p][2], a[p][3]);

        // left census -> registers
        census4g(left + img_off, wx, la);
    }

    __syncthreads();   // 4-warp barrier: right census + pad visible

    unsigned cost = 0u, cnt = 0u;
    if (active) {
        const float dd[4] = {dv.x, dv.y, dv.z, dv.w};
        #pragma unroll
        for (int p = 0; p < 4; p++) {
            if (dd[p] > 0.0f) {
                int ti = (int)dd[p];
                ti = ti < 0 ? 0 : (ti > MAX_DISP - 1 ? MAX_DISP - 1 : ti);
                const uint4 R = sc[wx + p + ti];   // pad zeros == OOR case
                cost += __popc(la[p][0] ^ R.x) + __popc(la[p][1] ^ R.y) +
                        __popc(la[p][2] ^ R.z) + __popc(la[p][3] ^ R.w);
                cnt  += 1u;
            }
        }
    }

    // ---- Reduce: warp shfl -> smem atomics -> global ----
    #pragma unroll
    for (int off = 16; off > 0; off >>= 1) {
        cost += __shfl_down_sync(0xFFFFFFFFu, cost, off);
        cnt  += __shfl_down_sync(0xFFFFFFFFu, cnt,  off);
    }
    if ((tid & 31) == 0) {
        atomicAdd(&s_red[0], cost);
        atomicAdd(&s_red[1], cnt);
    }
    __syncthreads();

    if (tid == 0) {
        atomicAdd(&g_acc[0], s_red[0]);
        atomicAdd(&g_acc[1], s_red[1]);
        __threadfence();
        const unsigned prev = atomicAdd(&g_done, 1u);
        if (prev == NBLOCKS - 1u) {
            const unsigned tc = atomicAdd(&g_acc[0], 0u);
            const unsigned tn = atomicAdd(&g_acc[1], 0u);
            out[0] = (float)tc / ((float)tn + 1e-6f);
            // reset for the next graph replay (visible at next kernel launch)
            g_acc[0] = 0u;
            g_acc[1] = 0u;
            g_done   = 0u;
        }
    }
}

extern "C" void kernel_launch(void* const* d_in, const int* in_sizes, int n_in,
                              void* d_out, int out_size) {
    const float* left  = (const float*)d_in[0];
    const float* right = (const float*)d_in[1];
    const float* disp  = (const float*)d_in[2];
    float* out = (float*)d_out;

    fused_census_loss<<<NBLOCKS, NTHREADS>>>(left, right, disp, out);
}